// round 3
// baseline (speedup 1.0000x reference)
#include <cuda_runtime.h>
#include <cuda_bf16.h>
#include <cfloat>

#define NA 8400
#define NB 32
#define NT 50
#define NK 10
#define NC 80

// ---- scratch (no allocations allowed: device globals) ----
__device__ float  g_obj_t[NB * NA];     // objectness targets (0/1)
__device__ float2 g_anchors[NA];        // anchor centers (image coords)
__device__ double g_acc[4];             // 0:num_pos 1:reg_sum 2:cls_sum 3:obj_sum

__device__ __forceinline__ void anchor_decode(int a, int& lvl, int& gx, int& gy,
                                              int& W, int& hw, float& s) {
    if (a < 6400)      { lvl = 0; W = 80; hw = 6400; gx = a % 80;            gy = a / 80;            s = 8.f;  }
    else if (a < 8000) { lvl = 1; W = 40; hw = 1600; int al = a - 6400; gx = al % 40; gy = al / 40; s = 16.f; }
    else               { lvl = 2; W = 20; hw = 400;  int al = a - 8000; gx = al % 20; gy = al / 20; s = 32.f; }
}

__device__ __forceinline__ float bce(float x, float t) {
    // BCEWithLogits, numerically stable: max(x,0) - x*t + log1p(exp(-|x|))
    return fmaxf(x, 0.f) - x * t + log1pf(expf(-fabsf(x)));
}

// ---- kernel 0: init scratch ----
__global__ void k_init() {
    int i = blockIdx.x * blockDim.x + threadIdx.x;
    int stride = gridDim.x * blockDim.x;
    if (i < 4) g_acc[i] = 0.0;
    for (int j = i; j < NB * NA; j += stride) g_obj_t[j] = 0.f;
    for (int j = i; j < NA; j += stride) {
        int lvl, gx, gy, W, hw; float s;
        anchor_decode(j, lvl, gx, gy, W, hw, s);
        g_anchors[j] = make_float2((float)gx * s + 0.5f * s, (float)gy * s + 0.5f * s);
    }
}

// ---- kernel 1: one warp per (b,t): top-10 anchors, IoU/CIoU, reg+cls loss, obj targets ----
__global__ void __launch_bounds__(128) k_assign(
    const float* __restrict__ p3_cls, const float* __restrict__ p3_reg,
    const float* __restrict__ p4_cls, const float* __restrict__ p4_reg,
    const float* __restrict__ p5_cls, const float* __restrict__ p5_reg,
    const float* __restrict__ targets)
{
    const unsigned FULL = 0xffffffffu;
    int wg   = (blockIdx.x * blockDim.x + threadIdx.x) >> 5;
    int lane = threadIdx.x & 31;
    if (wg >= NB * NT) return;
    int b = wg / NT;
    const float* tgt = targets + wg * 5;
    float tw = tgt[2], th = tgt[3];
    float tcx = tgt[0] + 0.5f * tw;
    float tcy = tgt[1] + 0.5f * th;
    int tcls = (int)tgt[4];

    // ---- per-lane top-10 (sorted asc by (dist, idx)) ----
    float d[NK]; int id[NK];
#pragma unroll
    for (int j = 0; j < NK; j++) { d[j] = FLT_MAX; id[j] = 0x7FFFFFFF; }

    for (int a = lane; a < NA; a += 32) {
        float2 c = g_anchors[a];
        // explicit non-fma ops + rn sqrt to match XLA's separate mul/add/sqrt
        float dx = __fsub_rn(c.x, tcx);
        float dy = __fsub_rn(c.y, tcy);
        float dist = __fsqrt_rn(__fadd_rn(__fmul_rn(dx, dx), __fmul_rn(dy, dy)));
        if (dist < d[NK - 1]) {          // equal-dist later index never belongs ahead
            float cd = dist; int ci = a;
#pragma unroll
            for (int j = 0; j < NK; j++) {
                bool sw = (cd < d[j]) || (cd == d[j] && ci < id[j]);
                if (sw) { float td = d[j]; int ti = id[j]; d[j] = cd; id[j] = ci; cd = td; ci = ti; }
            }
        }
    }

    // ---- warp merge: 10 rounds of lexicographic min, stable (dist asc, idx asc) ----
    int res_a = 0;   // lane k holds the rank-k anchor index
#pragma unroll 1
    for (int k = 0; k < NK; k++) {
        float bd = d[0]; int bi = id[0];
#pragma unroll
        for (int off = 16; off; off >>= 1) {
            float od = __shfl_xor_sync(FULL, bd, off);
            int   oi = __shfl_xor_sync(FULL, bi, off);
            if (od < bd || (od == bd && oi < bi)) { bd = od; bi = oi; }
        }
        if (id[0] == bi) {               // anchor indices unique across lanes
#pragma unroll
            for (int j = 0; j < NK - 1; j++) { d[j] = d[j + 1]; id[j] = id[j + 1]; }
            d[NK - 1] = FLT_MAX; id[NK - 1] = 0x7FFFFFFF;
        }
        if (lane == k) res_a = bi;
    }

    // ---- stage 2: lane k (<10) decodes its anchor's pred box, IoU + CIoU ----
    bool have = (lane < NK);
    float iou = -FLT_MAX, ciou = 0.f;
    int my_a = res_a;
    if (have) {
        int lvl, gx, gy, W, hw; float s;
        anchor_decode(my_a, lvl, gx, gy, W, hw, s);
        const float* regp = (lvl == 0) ? p3_reg : (lvl == 1) ? p4_reg : p5_reg;
        int base = (b * 4) * hw + gy * W + gx;
        float r0 = regp[base];
        float r1 = regp[base + hw];
        float r2 = regp[base + 2 * hw];
        float r3 = regp[base + 3 * hw];
        float pcx = ((float)gx + 1.f / (1.f + expf(-r0))) * s;
        float pcy = ((float)gy + 1.f / (1.f + expf(-r1))) * s;
        float pw  = expf(r2) * s;
        float ph  = expf(r3) * s;
        // corners (box1 = pred, box2 = target), exactly the reference's sequence
        float x11 = pcx - pw * 0.5f, x12 = pcx + pw * 0.5f;
        float y11 = pcy - ph * 0.5f, y12 = pcy + ph * 0.5f;
        float x21 = tcx - tw * 0.5f, x22 = tcx + tw * 0.5f;
        float y21 = tcy - th * 0.5f, y22 = tcy + th * 0.5f;
        float iw = fmaxf(fminf(x12, x22) - fmaxf(x11, x21), 0.f);
        float ih = fmaxf(fminf(y12, y22) - fmaxf(y11, y21), 0.f);
        float inter = iw * ih;
        float a1 = (x12 - x11) * (y12 - y11);
        float a2 = (x22 - x21) * (y22 - y21);
        float uni = a1 + a2 - inter + 1e-7f;
        iou = inter / uni;
        float cw = fmaxf(x12, x22) - fminf(x11, x21);
        float chh = fmaxf(y12, y22) - fminf(y11, y21);
        float c2 = cw * cw + chh * chh + 1e-7f;
        float ddx = x21 + x22 - x11 - x12;
        float ddy = y21 + y22 - y11 - y12;
        float rho2 = (ddx * ddx + ddy * ddy) * 0.25f;
        float dv = atanf((x22 - x21) / ((y22 - y21) + 1e-7f))
                 - atanf((x12 - x11) / ((y12 - y11) + 1e-7f));
        float v = (float)(4.0 / (3.14159 * 3.14159)) * dv * dv;
        float alpha = v / ((1.f - iou) + v + 1e-7f);
        ciou = iou - (rho2 / c2 + v * alpha);
    }

    // ---- argmax(iou) over k, first-max tie-break (matches jnp.argmax) ----
    float am = iou; int amk = lane;
#pragma unroll
    for (int off = 16; off; off >>= 1) {
        float om = __shfl_xor_sync(FULL, am, off);
        int   ok = __shfl_xor_sync(FULL, amk, off);
        if (om > am || (om == am && ok < amk)) { am = om; amk = ok; }
    }

    unsigned vb = __ballot_sync(FULL, have && (iou > 0.1f));
    bool w = have && (vb ? (iou > 0.1f) : (lane == amk));
    unsigned wb = __ballot_sync(FULL, w);

    float regc = w ? (1.f - ciou) : 0.f;
#pragma unroll
    for (int off = 16; off; off >>= 1) regc += __shfl_xor_sync(FULL, regc, off);
    if (lane == 0) {
        atomicAdd(&g_acc[0], (double)__popc(wb));   // num_pos
        atomicAdd(&g_acc[1], (double)regc);         // reg_sum
    }
    if (w) g_obj_t[b * NA + my_a] = 1.0f;           // scatter-max of {0,1}: plain store

    // ---- cls loss at assigned anchors: lanes sweep classes ----
    float clsacc = 0.f;
#pragma unroll 1
    for (int k = 0; k < NK; k++) {
        int ak = __shfl_sync(FULL, my_a, k);        // all lanes participate in shfl
        if (!((wb >> k) & 1)) continue;
        int lvl, gx, gy, W, hw; float s;
        anchor_decode(ak, lvl, gx, gy, W, hw, s);
        const float* clsp = (lvl == 0) ? p3_cls : (lvl == 1) ? p4_cls : p5_cls;
        int base = (b * NC) * hw + gy * W + gx;
        for (int c = lane; c < NC; c += 32) {
            float x = clsp[base + c * hw];
            float tt = (c == tcls) ? 1.f : 0.f;
            clsacc += bce(x, tt);
        }
    }
#pragma unroll
    for (int off = 16; off; off >>= 1) clsacc += __shfl_xor_sync(FULL, clsacc, off);
    if (lane == 0) atomicAdd(&g_acc[2], (double)clsacc);
}

// ---- kernel 2: objectness BCE over all B*A anchors ----
__global__ void __launch_bounds__(256) k_obj(const float* __restrict__ p3_obj,
                                             const float* __restrict__ p4_obj,
                                             const float* __restrict__ p5_obj)
{
    int i = blockIdx.x * blockDim.x + threadIdx.x;
    float acc = 0.f;
    if (i < NB * NA) {
        int b = i / NA, a = i - b * NA;
        float x;
        if (a < 6400)      x = p3_obj[b * 6400 + a];
        else if (a < 8000) x = p4_obj[b * 1600 + (a - 6400)];
        else               x = p5_obj[b * 400  + (a - 8000)];
        acc = bce(x, g_obj_t[i]);
    }
#pragma unroll
    for (int off = 16; off; off >>= 1) acc += __shfl_xor_sync(0xffffffffu, acc, off);
    __shared__ float sm[8];
    int lane = threadIdx.x & 31, wid = threadIdx.x >> 5;
    if (lane == 0) sm[wid] = acc;
    __syncthreads();
    if (wid == 0) {
        acc = (lane < 8) ? sm[lane] : 0.f;
#pragma unroll
        for (int off = 4; off; off >>= 1) acc += __shfl_xor_sync(0xffffffffu, acc, off);
        if (lane == 0) atomicAdd(&g_acc[3], (double)acc);
    }
}

// ---- kernel 3: finalize ----
__global__ void k_final(float* __restrict__ out) {
    if (threadIdx.x == 0 && blockIdx.x == 0) {
        double np = g_acc[0];
        if (np < 1.0) np = 1.0;
        double reg_l = g_acc[1] / np;
        double cls_l = g_acc[2] / np;
        double obj_l = g_acc[3] / np;
        out[0] = (float)(5.0 * reg_l + obj_l + cls_l);
        out[1] = (float)reg_l;
        out[2] = (float)obj_l;
        out[3] = (float)cls_l;
    }
}

extern "C" void kernel_launch(void* const* d_in, const int* in_sizes, int n_in,
                              void* d_out, int out_size) {
    const float* p3_cls  = (const float*)d_in[0];
    const float* p3_reg  = (const float*)d_in[1];
    const float* p3_obj  = (const float*)d_in[2];
    const float* p4_cls  = (const float*)d_in[3];
    const float* p4_reg  = (const float*)d_in[4];
    const float* p4_obj  = (const float*)d_in[5];
    const float* p5_cls  = (const float*)d_in[6];
    const float* p5_reg  = (const float*)d_in[7];
    const float* p5_obj  = (const float*)d_in[8];
    const float* targets = (const float*)d_in[9];

    k_init<<<128, 256>>>();
    k_assign<<<(NB * NT + 3) / 4, 128>>>(p3_cls, p3_reg, p4_cls, p4_reg,
                                         p5_cls, p5_reg, targets);
    k_obj<<<(NB * NA + 255) / 256, 256>>>(p3_obj, p4_obj, p5_obj);
    k_final<<<1, 32>>>((float*)d_out);
}

// round 4
// speedup vs baseline: 5.2256x; 5.2256x over previous
#include <cuda_runtime.h>
#include <cuda_bf16.h>
#include <cfloat>

#define NA 8400
#define NB 32
#define NT 50
#define NK 10
#define NC 80
#define NCAND 108   // 3 levels * 6x6 window

// ---- persistent scratch (device globals; zero-initialized at load, and every
//      launch restores them to zero, so each call is deterministic) ----
__device__ float    g_obj_t[NB * NA];   // objectness targets (0/1); reset by k_obj
__device__ double   g_acc[4];           // 0:num_pos 1:reg_sum 2:cls_sum 3:obj_sum; reset by finalize
__device__ unsigned g_done;             // last-block counter; reset by finalize

__device__ __forceinline__ void anchor_decode(int a, int& lvl, int& gx, int& gy,
                                              int& W, int& hw, float& s) {
    if (a < 6400)      { lvl = 0; W = 80; hw = 6400; gx = a % 80;            gy = a / 80;            s = 8.f;  }
    else if (a < 8000) { lvl = 1; W = 40; hw = 1600; int al = a - 6400; gx = al % 40; gy = al / 40; s = 16.f; }
    else               { lvl = 2; W = 20; hw = 400;  int al = a - 8000; gx = al % 20; gy = al / 20; s = 32.f; }
}

__device__ __forceinline__ float bce(float x, float t) {
    return fmaxf(x, 0.f) - x * t + log1pf(expf(-fabsf(x)));
}

// window base: leftmost of the 6 nearest in-range columns/rows
__device__ __forceinline__ int win_base(float tc, float s, int W) {
    float u = tc / s - 0.5f;           // continuous grid coord of target center
    int f = (int)floorf(u) - 2;
    if (f < 0) f = 0;
    if (f > W - 6) f = W - 6;
    return f;
}

// ---- kernel 1: one warp per (b,t). 108 window candidates -> exact top-10,
//      CIoU + reg loss, cls loss, obj-target scatter. ----
__global__ void __launch_bounds__(256) k_assign(
    const float* __restrict__ p3_cls, const float* __restrict__ p3_reg,
    const float* __restrict__ p4_cls, const float* __restrict__ p4_reg,
    const float* __restrict__ p5_cls, const float* __restrict__ p5_reg,
    const float* __restrict__ targets)
{
    const unsigned FULL = 0xffffffffu;
    int wid_in_blk = threadIdx.x >> 5;
    int wg   = blockIdx.x * 8 + wid_in_blk;     // grid sized exactly NB*NT warps
    int lane = threadIdx.x & 31;
    int b = wg / NT;
    const float* tgt = targets + wg * 5;
    float tw = tgt[2], th = tgt[3];
    float tcx = tgt[0] + 0.5f * tw;
    float tcy = tgt[1] + 0.5f * th;
    int tcls = (int)tgt[4];

    // window bases per level
    int x0a = win_base(tcx,  8.f, 80), y0a = win_base(tcy,  8.f, 80);
    int x0b = win_base(tcx, 16.f, 40), y0b = win_base(tcy, 16.f, 40);
    int x0c = win_base(tcx, 32.f, 20), y0c = win_base(tcy, 32.f, 20);

    // per-lane sorted-4 candidate list (asc by (dist, idx))
    float cd[4]; int ci[4];
#pragma unroll
    for (int j = 0; j < 4; j++) { cd[j] = FLT_MAX; ci[j] = 0x7FFFFFFF; }

#pragma unroll
    for (int t = 0; t < 4; t++) {
        int c = lane + (t << 5);
        if (c >= NCAND) break;
        int lvl = (c >= 72) ? 2 : (c >= 36) ? 1 : 0;
        int w6 = c - 36 * lvl;
        int dxi = w6 % 6, dyi = w6 / 6;
        int gx, gy, W, basei; float s;
        if (lvl == 0)      { gx = x0a + dxi; gy = y0a + dyi; W = 80; basei = 0;    s = 8.f;  }
        else if (lvl == 1) { gx = x0b + dxi; gy = y0b + dyi; W = 40; basei = 6400; s = 16.f; }
        else               { gx = x0c + dxi; gy = y0c + dyi; W = 20; basei = 8000; s = 32.f; }
        int idx = basei + gy * W + gx;
        float acx = (float)gx * s + 0.5f * s;   // exact, matches grids*strides + strides/2
        float acy = (float)gy * s + 0.5f * s;
        float dx = __fsub_rn(acx, tcx);
        float dy = __fsub_rn(acy, tcy);
        float dist = __fsqrt_rn(__fadd_rn(__fmul_rn(dx, dx), __fmul_rn(dy, dy)));
        // insert into sorted-4
        float vcd = dist; int vci = idx;
#pragma unroll
        for (int j = 0; j < 4; j++) {
            bool sw = (vcd < cd[j]) || (vcd == cd[j] && vci < ci[j]);
            if (sw) { float td = cd[j]; int ti = ci[j]; cd[j] = vcd; ci[j] = vci; vcd = td; vci = ti; }
        }
    }

    // warp merge: 10 rounds of lexicographic min (dist asc, idx asc)
    int res_a = 0;
#pragma unroll 1
    for (int k = 0; k < NK; k++) {
        float bd = cd[0]; int bi = ci[0];
#pragma unroll
        for (int off = 16; off; off >>= 1) {
            float od = __shfl_xor_sync(FULL, bd, off);
            int   oi = __shfl_xor_sync(FULL, bi, off);
            if (od < bd || (od == bd && oi < bi)) { bd = od; bi = oi; }
        }
        if (ci[0] == bi) {          // anchor indices unique across candidates
#pragma unroll
            for (int j = 0; j < 3; j++) { cd[j] = cd[j + 1]; ci[j] = ci[j + 1]; }
            cd[3] = FLT_MAX; ci[3] = 0x7FFFFFFF;
        }
        if (lane == k) res_a = bi;
    }

    // stage 2: lane k (<10) decodes pred box at its anchor, IoU + CIoU
    bool have = (lane < NK);
    float iou = -FLT_MAX, ciou = 0.f;
    int my_a = res_a;
    if (have) {
        int lvl, gx, gy, W, hw; float s;
        anchor_decode(my_a, lvl, gx, gy, W, hw, s);
        const float* regp = (lvl == 0) ? p3_reg : (lvl == 1) ? p4_reg : p5_reg;
        int base = (b * 4) * hw + gy * W + gx;
        float r0 = regp[base];
        float r1 = regp[base + hw];
        float r2 = regp[base + 2 * hw];
        float r3 = regp[base + 3 * hw];
        float pcx = ((float)gx + 1.f / (1.f + expf(-r0))) * s;
        float pcy = ((float)gy + 1.f / (1.f + expf(-r1))) * s;
        float pw  = expf(r2) * s;
        float ph  = expf(r3) * s;
        float x11 = pcx - pw * 0.5f, x12 = pcx + pw * 0.5f;
        float y11 = pcy - ph * 0.5f, y12 = pcy + ph * 0.5f;
        float x21 = tcx - tw * 0.5f, x22 = tcx + tw * 0.5f;
        float y21 = tcy - th * 0.5f, y22 = tcy + th * 0.5f;
        float iw = fmaxf(fminf(x12, x22) - fmaxf(x11, x21), 0.f);
        float ih = fmaxf(fminf(y12, y22) - fmaxf(y11, y21), 0.f);
        float inter = iw * ih;
        float a1 = (x12 - x11) * (y12 - y11);
        float a2 = (x22 - x21) * (y22 - y21);
        float uni = a1 + a2 - inter + 1e-7f;
        iou = inter / uni;
        float cw = fmaxf(x12, x22) - fminf(x11, x21);
        float chh = fmaxf(y12, y22) - fminf(y11, y21);
        float c2 = cw * cw + chh * chh + 1e-7f;
        float ddx = x21 + x22 - x11 - x12;
        float ddy = y21 + y22 - y11 - y12;
        float rho2 = (ddx * ddx + ddy * ddy) * 0.25f;
        float dv = atanf((x22 - x21) / ((y22 - y21) + 1e-7f))
                 - atanf((x12 - x11) / ((y12 - y11) + 1e-7f));
        float v = (float)(4.0 / (3.14159 * 3.14159)) * dv * dv;
        float alpha = v / ((1.f - iou) + v + 1e-7f);
        ciou = iou - (rho2 / c2 + v * alpha);
    }

    // argmax(iou) over K with first-max tie-break
    float am = iou; int amk = lane;
#pragma unroll
    for (int off = 16; off; off >>= 1) {
        float om = __shfl_xor_sync(FULL, am, off);
        int   ok = __shfl_xor_sync(FULL, amk, off);
        if (om > am || (om == am && ok < amk)) { am = om; amk = ok; }
    }

    unsigned vb = __ballot_sync(FULL, have && (iou > 0.1f));
    bool w = have && (vb ? (iou > 0.1f) : (lane == amk));
    unsigned wb = __ballot_sync(FULL, w);

    float regc = w ? (1.f - ciou) : 0.f;
#pragma unroll
    for (int off = 16; off; off >>= 1) regc += __shfl_xor_sync(FULL, regc, off);
    if (w) g_obj_t[b * NA + my_a] = 1.0f;   // scatter-max of {0,1}: plain store

    // cls loss at assigned anchors: lanes sweep classes
    float clsacc = 0.f;
#pragma unroll 1
    for (int k = 0; k < NK; k++) {
        int ak = __shfl_sync(FULL, my_a, k);
        if (!((wb >> k) & 1)) continue;
        int lvl, gx, gy, W, hw; float s;
        anchor_decode(ak, lvl, gx, gy, W, hw, s);
        const float* clsp = (lvl == 0) ? p3_cls : (lvl == 1) ? p4_cls : p5_cls;
        int base = (b * NC) * hw + gy * W + gx;
        for (int c = lane; c < NC; c += 32) {
            float x = clsp[base + c * hw];
            float tt = (c == tcls) ? 1.f : 0.f;
            clsacc += bce(x, tt);
        }
    }
#pragma unroll
    for (int off = 16; off; off >>= 1) clsacc += __shfl_xor_sync(FULL, clsacc, off);

    // block-level reduction -> 3 double atomics per block
    __shared__ float s_np[8], s_reg[8], s_cls[8];
    if (lane == 0) {
        s_np[wid_in_blk]  = (float)__popc(wb);
        s_reg[wid_in_blk] = regc;
        s_cls[wid_in_blk] = clsacc;
    }
    __syncthreads();
    if (wid_in_blk == 0 && lane < 8) {
        float vnp = s_np[lane], vrg = s_reg[lane], vcl = s_cls[lane];
#pragma unroll
        for (int off = 4; off; off >>= 1) {
            vnp += __shfl_xor_sync(0xffu, vnp, off);
            vrg += __shfl_xor_sync(0xffu, vrg, off);
            vcl += __shfl_xor_sync(0xffu, vcl, off);
        }
        if (lane == 0) {
            atomicAdd(&g_acc[0], (double)vnp);
            atomicAdd(&g_acc[1], (double)vrg);
            atomicAdd(&g_acc[2], (double)vcl);
        }
    }
}

// ---- kernel 2: objectness BCE over all B*A anchors + fused finalize.
//      Also resets g_obj_t for the next call. ----
__global__ void __launch_bounds__(256) k_obj(const float* __restrict__ p3_obj,
                                             const float* __restrict__ p4_obj,
                                             const float* __restrict__ p5_obj,
                                             float* __restrict__ out)
{
    float acc = 0.f;
    int stride = gridDim.x * blockDim.x;
    for (int i = blockIdx.x * blockDim.x + threadIdx.x; i < NB * NA; i += stride) {
        int b = i / NA, a = i - b * NA;
        float x;
        if (a < 6400)      x = p3_obj[b * 6400 + a];
        else if (a < 8000) x = p4_obj[b * 1600 + (a - 6400)];
        else               x = p5_obj[b * 400  + (a - 8000)];
        acc += bce(x, g_obj_t[i]);
        g_obj_t[i] = 0.f;                 // reset for next launch
    }
#pragma unroll
    for (int off = 16; off; off >>= 1) acc += __shfl_xor_sync(0xffffffffu, acc, off);
    __shared__ float sm[8];
    int lane = threadIdx.x & 31, wid = threadIdx.x >> 5;
    if (lane == 0) sm[wid] = acc;
    __syncthreads();
    if (wid == 0) {
        acc = (lane < 8) ? sm[lane] : 0.f;
#pragma unroll
        for (int off = 4; off; off >>= 1) acc += __shfl_xor_sync(0xffffffffu, acc, off);
        if (lane == 0) {
            atomicAdd(&g_acc[3], (double)acc);
            __threadfence();
            unsigned t = atomicAdd(&g_done, 1u);
            if (t == gridDim.x - 1) {     // last block: finalize + reset scratch
                double np  = atomicAdd(&g_acc[0], 0.0);
                double rg  = atomicAdd(&g_acc[1], 0.0);
                double cl  = atomicAdd(&g_acc[2], 0.0);
                double ob  = atomicAdd(&g_acc[3], 0.0);
                if (np < 1.0) np = 1.0;
                double reg_l = rg / np, cls_l = cl / np, obj_l = ob / np;
                out[0] = (float)(5.0 * reg_l + obj_l + cls_l);
                out[1] = (float)reg_l;
                out[2] = (float)obj_l;
                out[3] = (float)cls_l;
                g_acc[0] = 0.0; g_acc[1] = 0.0; g_acc[2] = 0.0; g_acc[3] = 0.0;
                g_done = 0u;
            }
        }
    }
}

extern "C" void kernel_launch(void* const* d_in, const int* in_sizes, int n_in,
                              void* d_out, int out_size) {
    const float* p3_cls  = (const float*)d_in[0];
    const float* p3_reg  = (const float*)d_in[1];
    const float* p3_obj  = (const float*)d_in[2];
    const float* p4_cls  = (const float*)d_in[3];
    const float* p4_reg  = (const float*)d_in[4];
    const float* p4_obj  = (const float*)d_in[5];
    const float* p5_cls  = (const float*)d_in[6];
    const float* p5_reg  = (const float*)d_in[7];
    const float* p5_obj  = (const float*)d_in[8];
    const float* targets = (const float*)d_in[9];

    k_assign<<<NB * NT / 8, 256>>>(p3_cls, p3_reg, p4_cls, p4_reg,
                                   p5_cls, p5_reg, targets);
    k_obj<<<264, 256>>>(p3_obj, p4_obj, p5_obj, (float*)d_out);
}

// round 6
// speedup vs baseline: 5.7300x; 1.0965x over previous
#include <cuda_runtime.h>
#include <cuda_bf16.h>
#include <cfloat>

#define NA 8400
#define NB 32
#define NT 50
#define NK 10
#define NC 80
#define NCAND 108          // 3 levels * 6x6 window
#define ASSIGN_BLOCKS 200  // 8 warps (targets) per block
#define BCE_V4 67200       // NB*NA/4 float4 obj elements
#define MAXPOS (NB * NT * NK)

// ---- persistent scratch (device globals; zero at load, every launch restores zero) ----
__device__ int      g_flag[NB * NA];   // dedup flags; reset by k_fin via g_list
__device__ int      g_list[MAXPOS];    // flagged indices + 1 (0 = unused); reset by k_fin
__device__ unsigned g_cnt;             // list cursor; reset by k_fin
__device__ double   g_acc[4];          // 0:num_pos 1:reg_sum 2:cls_sum 3:obj_sum; reset by k_fin

__device__ __forceinline__ void anchor_decode(int a, int& lvl, int& gx, int& gy,
                                              int& W, int& hw, float& s) {
    if (a < 6400)      { lvl = 0; W = 80; hw = 6400; gx = a % 80;            gy = a / 80;            s = 8.f;  }
    else if (a < 8000) { lvl = 1; W = 40; hw = 1600; int al = a - 6400; gx = al % 40; gy = al / 40; s = 16.f; }
    else               { lvl = 2; W = 20; hw = 400;  int al = a - 8000; gx = al % 20; gy = al / 20; s = 32.f; }
}

// BCEWithLogits, target 0, fast-math (feeds only the final sum, not selection)
__device__ __forceinline__ float bce0(float x) {
    return fmaxf(x, 0.f) + __logf(1.f + __expf(-fabsf(x)));
}
// BCEWithLogits, arbitrary target
__device__ __forceinline__ float bce(float x, float t) {
    return fmaxf(x, 0.f) - x * t + __logf(1.f + __expf(-fabsf(x)));
}

// leftmost of the 6 nearest in-range columns/rows
__device__ __forceinline__ int win_base(float tc, float s, int W) {
    float u = tc / s - 0.5f;
    int f = (int)floorf(u) - 2;
    if (f < 0) f = 0;
    if (f > W - 6) f = W - 6;
    return f;
}

// ---- kernel 1: fused. Blocks [0,200): one warp per (b,t) assignment + reg/cls loss
//      + obj correction (-x at unique assigned anchors, deduped via g_flag).
//      Blocks [200, 200+263): vectorized sum of bce(x, 0) over ALL obj preds. ----
__global__ void __launch_bounds__(256) k_main(
    const float* __restrict__ p3_cls, const float* __restrict__ p3_reg, const float* __restrict__ p3_obj,
    const float* __restrict__ p4_cls, const float* __restrict__ p4_reg, const float* __restrict__ p4_obj,
    const float* __restrict__ p5_cls, const float* __restrict__ p5_reg, const float* __restrict__ p5_obj,
    const float* __restrict__ targets)
{
    const unsigned FULL = 0xffffffffu;
    int lane = threadIdx.x & 31;
    int wid_in_blk = threadIdx.x >> 5;

    if (blockIdx.x >= ASSIGN_BLOCKS) {
        // ======== background objectness BCE: bce(x, 0) over all B*A anchors ========
        int v = (blockIdx.x - ASSIGN_BLOCKS) * 256 + threadIdx.x;
        float acc = 0.f;
        if (v < BCE_V4) {
            const float4* p; int off;
            if (v < 51200)      { p = (const float4*)p3_obj; off = v; }
            else if (v < 64000) { p = (const float4*)p4_obj; off = v - 51200; }
            else                { p = (const float4*)p5_obj; off = v - 64000; }
            float4 x4 = p[off];
            acc = bce0(x4.x) + bce0(x4.y) + bce0(x4.z) + bce0(x4.w);
        }
#pragma unroll
        for (int off = 16; off; off >>= 1) acc += __shfl_xor_sync(FULL, acc, off);
        __shared__ float sm[8];
        if (lane == 0) sm[wid_in_blk] = acc;
        __syncthreads();
        if (wid_in_blk == 0) {
            acc = (lane < 8) ? sm[lane] : 0.f;
#pragma unroll
            for (int off = 4; off; off >>= 1) acc += __shfl_xor_sync(FULL, acc, off);
            if (lane == 0) atomicAdd(&g_acc[3], (double)acc);
        }
        return;
    }

    // ======== assignment path: one warp per (b,t) ========
    int wg = blockIdx.x * 8 + wid_in_blk;
    int b = wg / NT;
    const float* tgt = targets + wg * 5;
    float tw = tgt[2], th = tgt[3];
    float tcx = tgt[0] + 0.5f * tw;
    float tcy = tgt[1] + 0.5f * th;
    int tcls = (int)tgt[4];

    int x0a = win_base(tcx,  8.f, 80), y0a = win_base(tcy,  8.f, 80);
    int x0b = win_base(tcx, 16.f, 40), y0b = win_base(tcy, 16.f, 40);
    int x0c = win_base(tcx, 32.f, 20), y0c = win_base(tcy, 32.f, 20);

    // per-lane sorted-4 candidates (asc by (dist, idx)); window provably contains top-10
    float cd[4]; int ci[4];
#pragma unroll
    for (int j = 0; j < 4; j++) { cd[j] = FLT_MAX; ci[j] = 0x7FFFFFFF; }

#pragma unroll
    for (int t = 0; t < 4; t++) {
        int c = lane + (t << 5);
        if (c >= NCAND) break;
        int lvl = (c >= 72) ? 2 : (c >= 36) ? 1 : 0;
        int w6 = c - 36 * lvl;
        int dxi = w6 % 6, dyi = w6 / 6;
        int gx, gy, W, basei; float s;
        if (lvl == 0)      { gx = x0a + dxi; gy = y0a + dyi; W = 80; basei = 0;    s = 8.f;  }
        else if (lvl == 1) { gx = x0b + dxi; gy = y0b + dyi; W = 40; basei = 6400; s = 16.f; }
        else               { gx = x0c + dxi; gy = y0c + dyi; W = 20; basei = 8000; s = 32.f; }
        int idx = basei + gy * W + gx;
        float acx = (float)gx * s + 0.5f * s;
        float acy = (float)gy * s + 0.5f * s;
        float dx = __fsub_rn(acx, tcx);
        float dy = __fsub_rn(acy, tcy);
        float dist = __fsqrt_rn(__fadd_rn(__fmul_rn(dx, dx), __fmul_rn(dy, dy)));
        float vcd = dist; int vci = idx;
#pragma unroll
        for (int j = 0; j < 4; j++) {
            bool sw = (vcd < cd[j]) || (vcd == cd[j] && vci < ci[j]);
            if (sw) { float td = cd[j]; int ti = ci[j]; cd[j] = vcd; ci[j] = vci; vcd = td; vci = ti; }
        }
    }

    // warp merge: 10 rounds of stable lexicographic min
    int res_a = 0;
#pragma unroll 1
    for (int k = 0; k < NK; k++) {
        float bd = cd[0]; int bi = ci[0];
#pragma unroll
        for (int off = 16; off; off >>= 1) {
            float od = __shfl_xor_sync(FULL, bd, off);
            int   oi = __shfl_xor_sync(FULL, bi, off);
            if (od < bd || (od == bd && oi < bi)) { bd = od; bi = oi; }
        }
        if (ci[0] == bi) {
#pragma unroll
            for (int j = 0; j < 3; j++) { cd[j] = cd[j + 1]; ci[j] = ci[j + 1]; }
            cd[3] = FLT_MAX; ci[3] = 0x7FFFFFFF;
        }
        if (lane == k) res_a = bi;
    }

    // lane k (<10): decode pred box at its anchor, IoU + CIoU (selection-critical: precise math)
    bool have = (lane < NK);
    float iou = -FLT_MAX, ciou = 0.f;
    int my_a = res_a;
    int lvl = 0, gx = 0, gy = 0, W = 0, hw = 0; float s = 0.f;
    if (have) {
        anchor_decode(my_a, lvl, gx, gy, W, hw, s);
        const float* regp = (lvl == 0) ? p3_reg : (lvl == 1) ? p4_reg : p5_reg;
        int base = (b * 4) * hw + gy * W + gx;
        float r0 = regp[base];
        float r1 = regp[base + hw];
        float r2 = regp[base + 2 * hw];
        float r3 = regp[base + 3 * hw];
        float pcx = ((float)gx + 1.f / (1.f + expf(-r0))) * s;
        float pcy = ((float)gy + 1.f / (1.f + expf(-r1))) * s;
        float pw  = expf(r2) * s;
        float ph  = expf(r3) * s;
        float x11 = pcx - pw * 0.5f, x12 = pcx + pw * 0.5f;
        float y11 = pcy - ph * 0.5f, y12 = pcy + ph * 0.5f;
        float x21 = tcx - tw * 0.5f, x22 = tcx + tw * 0.5f;
        float y21 = tcy - th * 0.5f, y22 = tcy + th * 0.5f;
        float iw = fmaxf(fminf(x12, x22) - fmaxf(x11, x21), 0.f);
        float ih = fmaxf(fminf(y12, y22) - fmaxf(y11, y21), 0.f);
        float inter = iw * ih;
        float a1 = (x12 - x11) * (y12 - y11);
        float a2 = (x22 - x21) * (y22 - y21);
        float uni = a1 + a2 - inter + 1e-7f;
        iou = inter / uni;
        float cw = fmaxf(x12, x22) - fminf(x11, x21);
        float chh = fmaxf(y12, y22) - fminf(y11, y21);
        float c2 = cw * cw + chh * chh + 1e-7f;
        float ddx = x21 + x22 - x11 - x12;
        float ddy = y21 + y22 - y11 - y12;
        float rho2 = (ddx * ddx + ddy * ddy) * 0.25f;
        float dv = atanf((x22 - x21) / ((y22 - y21) + 1e-7f))
                 - atanf((x12 - x11) / ((y12 - y11) + 1e-7f));
        float v = (float)(4.0 / (3.14159 * 3.14159)) * dv * dv;
        float alpha = v / ((1.f - iou) + v + 1e-7f);
        ciou = iou - (rho2 / c2 + v * alpha);
    }

    // argmax(iou) over K, first-max tie-break
    float am = iou; int amk = lane;
#pragma unroll
    for (int off = 16; off; off >>= 1) {
        float om = __shfl_xor_sync(FULL, am, off);
        int   ok = __shfl_xor_sync(FULL, amk, off);
        if (om > am || (om == am && ok < amk)) { am = om; amk = ok; }
    }

    unsigned vb = __ballot_sync(FULL, have && (iou > 0.1f));
    bool w = have && (vb ? (iou > 0.1f) : (lane == amk));
    unsigned wb = __ballot_sync(FULL, w);

    float regc = w ? (1.f - ciou) : 0.f;
#pragma unroll
    for (int off = 16; off; off >>= 1) regc += __shfl_xor_sync(FULL, regc, off);

    // obj correction: bce(x,1)-bce(x,0) == -x at each UNIQUE assigned (b,anchor)
    float corr = 0.f;
    if (w) {
        int i = b * NA + my_a;
        if (atomicExch(&g_flag[i], 1) == 0) {
            unsigned pos = atomicAdd(&g_cnt, 1u);
            g_list[pos] = i + 1;                    // +1 so 0 means "unused"
            const float* objp = (lvl == 0) ? p3_obj : (lvl == 1) ? p4_obj : p5_obj;
            corr = -objp[b * hw + gy * W + gx];
        }
    }
#pragma unroll
    for (int off = 16; off; off >>= 1) corr += __shfl_xor_sync(FULL, corr, off);

    // cls loss at assigned anchors: lanes sweep classes
    float clsacc = 0.f;
#pragma unroll 1
    for (int k = 0; k < NK; k++) {
        int ak = __shfl_sync(FULL, my_a, k);
        if (!((wb >> k) & 1)) continue;
        int l2, gx2, gy2, W2, hw2; float s2;
        anchor_decode(ak, l2, gx2, gy2, W2, hw2, s2);
        const float* clsp = (l2 == 0) ? p3_cls : (l2 == 1) ? p4_cls : p5_cls;
        int base = (b * NC) * hw2 + gy2 * W2 + gx2;
        for (int c = lane; c < NC; c += 32) {
            float x = clsp[base + c * hw2];
            clsacc += bce(x, (c == tcls) ? 1.f : 0.f);
        }
    }
#pragma unroll
    for (int off = 16; off; off >>= 1) clsacc += __shfl_xor_sync(FULL, clsacc, off);

    // block reduction -> 4 double atomics per block
    __shared__ float s_np[8], s_reg[8], s_cls[8], s_obj[8];
    if (lane == 0) {
        s_np[wid_in_blk]  = (float)__popc(wb);
        s_reg[wid_in_blk] = regc;
        s_cls[wid_in_blk] = clsacc;
        s_obj[wid_in_blk] = corr;
    }
    __syncthreads();
    if (wid_in_blk == 0 && lane < 8) {
        float vnp = s_np[lane], vrg = s_reg[lane], vcl = s_cls[lane], vob = s_obj[lane];
#pragma unroll
        for (int off = 4; off; off >>= 1) {
            vnp += __shfl_xor_sync(0xffu, vnp, off);
            vrg += __shfl_xor_sync(0xffu, vrg, off);
            vcl += __shfl_xor_sync(0xffu, vcl, off);
            vob += __shfl_xor_sync(0xffu, vob, off);
        }
        if (lane == 0) {
            atomicAdd(&g_acc[0], (double)vnp);
            atomicAdd(&g_acc[1], (double)vrg);
            atomicAdd(&g_acc[2], (double)vcl);
            atomicAdd(&g_acc[3], (double)vob);
        }
    }
}

// ---- kernel 2: finalize + reset scratch (flags via list, list, cnt, acc) ----
__global__ void __launch_bounds__(256) k_fin(float* __restrict__ out) {
    int tid = blockIdx.x * 256 + threadIdx.x;
    if (tid < MAXPOS) {
        int v = g_list[tid];
        if (v) { g_flag[v - 1] = 0; g_list[tid] = 0; }
    }
    if (tid == 0) {
        double np = g_acc[0];
        double rg = g_acc[1];
        double cl = g_acc[2];
        double ob = g_acc[3];
        if (np < 1.0) np = 1.0;
        double reg_l = rg / np, cls_l = cl / np, obj_l = ob / np;
        out[0] = (float)(5.0 * reg_l + obj_l + cls_l);
        out[1] = (float)reg_l;
        out[2] = (float)obj_l;
        out[3] = (float)cls_l;
        g_acc[0] = 0.0; g_acc[1] = 0.0; g_acc[2] = 0.0; g_acc[3] = 0.0;
        g_cnt = 0u;
    }
}

extern "C" void kernel_launch(void* const* d_in, const int* in_sizes, int n_in,
                              void* d_out, int out_size) {
    const float* p3_cls  = (const float*)d_in[0];
    const float* p3_reg  = (const float*)d_in[1];
    const float* p3_obj  = (const float*)d_in[2];
    const float* p4_cls  = (const float*)d_in[3];
    const float* p4_reg  = (const float*)d_in[4];
    const float* p4_obj  = (const float*)d_in[5];
    const float* p5_cls  = (const float*)d_in[6];
    const float* p5_reg  = (const float*)d_in[7];
    const float* p5_obj  = (const float*)d_in[8];
    const float* targets = (const float*)d_in[9];

    // 200 assign blocks + 263 bce blocks (263*256 = 67328 >= 67200 float4)
    k_main<<<ASSIGN_BLOCKS + 263, 256>>>(p3_cls, p3_reg, p3_obj,
                                         p4_cls, p4_reg, p4_obj,
                                         p5_cls, p5_reg, p5_obj, targets);
    k_fin<<<(MAXPOS + 255) / 256, 256>>>((float*)d_out);
}